// round 17
// baseline (speedup 1.0000x reference)
#include <cuda_runtime.h>
#include <cuda_fp16.h>
#include <cstdint>
#include <cstddef>

// Problem constants
#define NB   4096
#define NN   29
#define NC   6
#define CDIM 16
#define DD   22
#define HDIM 64
#define NL   2
#define NOUT 24
#define OUTROW 12
#define ZROW 25
#define PRU  40     // pi/pj row stride (uint32)
#define W2HW 136    // W2 smem row stride (uint32)
#define ZTU  20     // ztU row stride
#define CATU 52     // catshU row stride
#define HBU  36     // hbufU row stride
#define MAGU 32     // maggU row stride within plane
#define MPL  932    // magg plane stride

// Shared memory layout (float offsets)
#define OFF_Z    0        // 736
#define OFF_ZN   736      // 736
#define OFF_PI   1472     // 1280
#define OFF_PJ   2752     // 1280
#define OFF_W2H  4032     // 4352
#define OFF_ZT   8384     // 640
#define OFF_MAGG 9024     // 3728
#define OFF_H    12752    // 1152
#define OFF_EBH  13904    // 64 (both layers)
#define OFF_GWH  13968    // 64 (both layers)
#define SMEM_FLOATS 14032 // 56128 bytes -> 4 CTAs/SM
// catshU [32][52]=1664 uint aliases OFF_PI..3136

// Prepacked fp16 weights (device scratch; filled by prep_pack each launch)
__device__ uint32_t g_eW1p[NL * 2 * 12 * 64];
__device__ uint32_t g_eW2p[NL * 32 * 64];
__device__ uint32_t g_nW1p[NL * 44 * 64];
__device__ uint32_t g_nW2p[NL * 32 * 24];

__device__ __forceinline__ float tanhfast(float x) {
    float y;
    asm("tanh.approx.f32 %0, %1;" : "=f"(y) : "f"(x));
    return y;
}
__device__ __forceinline__ float silu_t(float v) {
    float h = 0.5f * v;
    return fmaf(h, tanhfast(h), h);
}
__device__ __forceinline__ float sigm_t(float v) {
    return fmaf(0.5f, tanhfast(0.5f * v), 0.5f);
}
__device__ __forceinline__ uint32_t pack_h2(float lo, float hi) {
    __half2 h = __floats2half2_rn(lo, hi);
    return *(uint32_t*)&h;
}
__device__ __forceinline__ uint32_t hadd2u(uint32_t a, uint32_t b) {
    __half2 r = __hadd2(*(__half2*)&a, *(__half2*)&b);
    return *(uint32_t*)&r;
}
__device__ __forceinline__ uint32_t hfma2u(uint32_t a, uint32_t b, uint32_t c) {
    __half2 r = __hfma2(*(__half2*)&a, *(__half2*)&b, *(__half2*)&c);
    return *(uint32_t*)&r;
}
__device__ __forceinline__ uint32_t hmul2u(uint32_t a, uint32_t b) {
    __half2 r = __hmul2(*(__half2*)&a, *(__half2*)&b);
    return *(uint32_t*)&r;
}
// silu(2h) given h: h + h*tanh(h)
__device__ __forceinline__ uint32_t silu_from_h(uint32_t h) {
    uint32_t tu;
    asm("tanh.approx.f16x2 %0, %1;" : "=r"(tu) : "r"(h));
    return hfma2u(h, tu, h);
}
__device__ __forceinline__ float2 h22f2(uint32_t u) {
    return __half22float2(*(__half2*)&u);
}
__device__ __forceinline__ uint32_t bcast_h2(float v) {
    __half2 h = __float2half2_rn(v);
    return *(uint32_t*)&h;
}
__device__ __forceinline__ void mma_f16(float c[4], uint32_t a0, uint32_t a1,
                                        uint32_t a2, uint32_t a3,
                                        uint32_t b0, uint32_t b1) {
    asm volatile(
        "mma.sync.aligned.m16n8k16.row.col.f32.f16.f16.f32 "
        "{%0,%1,%2,%3}, {%4,%5,%6,%7}, {%8,%9}, {%0,%1,%2,%3};\n"
        : "+f"(c[0]), "+f"(c[1]), "+f"(c[2]), "+f"(c[3])
        : "r"(a0), "r"(a1), "r"(a2), "r"(a3), "r"(b0), "r"(b1));
}
__device__ __forceinline__ void mma_f16_k8(float c[4], uint32_t a0, uint32_t a1,
                                           uint32_t b0) {
    asm volatile(
        "mma.sync.aligned.m16n8k8.row.col.f32.f16.f16.f32 "
        "{%0,%1,%2,%3}, {%4,%5}, {%6}, {%0,%1,%2,%3};\n"
        : "+f"(c[0]), "+f"(c[1]), "+f"(c[2]), "+f"(c[3])
        : "r"(a0), "r"(a1), "r"(b0));
}

// ---- prep: pack weights to half2 once per launch ----
extern "C" __global__ void prep_pack(const float* __restrict__ eW1,
                                     const float* __restrict__ eW2,
                                     const float* __restrict__ nW1,
                                     const float* __restrict__ nW2) {
    int tid = blockIdx.x * blockDim.x + threadIdx.x;
    int stride = gridDim.x * blockDim.x;
    for (int i = tid; i < NL * 2 * 12 * 64; i += stride) {
        int c = i & 63;
        int p = (i >> 6) % 12;
        int h = ((i >> 6) / 12) & 1;
        int l = (i >> 6) / 24;
        int k0 = 2 * p;
        float v0 = (k0 < DD)     ? eW1[(l * 2 * DD + h * DD + k0) * HDIM + c] : 0.f;
        float v1 = (k0 + 1 < DD) ? eW1[(l * 2 * DD + h * DD + k0 + 1) * HDIM + c] : 0.f;
        g_eW1p[i] = pack_h2(v0, v1);
    }
    for (int i = tid; i < NL * 32 * 64; i += stride) {
        int c = i & 63;
        int p = (i >> 6) & 31;
        int l = i >> 11;
        g_eW2p[i] = pack_h2(eW2[(l * HDIM + 2 * p) * HDIM + c],
                            eW2[(l * HDIM + 2 * p + 1) * HDIM + c]);
    }
    for (int i = tid; i < NL * 44 * 64; i += stride) {
        int c = i & 63;
        int p = (i >> 6) % 44;
        int l = (i >> 6) / 44;
        int k0 = 2 * p;
        const int KT = DD + HDIM;
        float v0 = (k0 < KT)     ? nW1[(l * KT + k0) * HDIM + c] : 0.f;
        float v1 = (k0 + 1 < KT) ? nW1[(l * KT + k0 + 1) * HDIM + c] : 0.f;
        g_nW1p[i] = pack_h2(v0, v1);
    }
    for (int i = tid; i < NL * 32 * 24; i += stride) {
        int d = i % 24;
        int p = (i / 24) & 31;
        int l = i / (32 * 24);
        float v0 = (d < DD) ? nW2[(l * HDIM + 2 * p) * DD + d] : 0.f;
        float v1 = (d < DD) ? nW2[(l * HDIM + 2 * p + 1) * DD + d] : 0.f;
        g_nW2p[i] = pack_h2(v0, v1);
    }
}

extern "C" __global__ void __launch_bounds__(256, 4)
gnn_kernel(const float* __restrict__ x,   const float* __restrict__ ctx,
           const float* __restrict__ eb1, const float* __restrict__ eb2,
           const float* __restrict__ gW,  const float* __restrict__ gb,
           const float* __restrict__ lng, const float* __restrict__ lnb,
           const float* __restrict__ nb1, const float* __restrict__ nb2,
           const float* __restrict__ hW1, const float* __restrict__ hb1,
           const float* __restrict__ hW2, const float* __restrict__ hb2,
           float* __restrict__ out)
{
    extern __shared__ float sh[];
    float*    zsh  = sh + OFF_Z;
    float*    znsh = sh + OFF_ZN;
    uint32_t* piU  = (uint32_t*)(sh + OFF_PI);
    uint32_t* pjU  = (uint32_t*)(sh + OFF_PJ);
    uint32_t* w2hU = (uint32_t*)(sh + OFF_W2H);
    uint32_t* ztU  = (uint32_t*)(sh + OFF_ZT);
    uint32_t* maggU = (uint32_t*)(sh + OFF_MAGG);   // [4 planes][29][32]
    uint32_t* hbufU = (uint32_t*)(sh + OFF_H);
    uint32_t* ebhU = (uint32_t*)(sh + OFF_EBH);     // [2 layers][32]
    uint32_t* gwhU = (uint32_t*)(sh + OFF_GWH);     // [2 layers][32]
    uint32_t* catshU = (uint32_t*)(sh + OFF_PI);

    const int b = blockIdx.x;
    const int t = threadIdx.x;
    const int w = t >> 5;
    const int lane = t & 31;
    const int lq = lane >> 2;
    const int cq = lane & 3;
    const int i_sel = w >> 1;
    const int jh = w & 1;
    const int r0 = jh * 16 + lq;
    const int r1 = r0 + 8;

    // ---- load z = concat(x, context) ----
    for (int idx = t; idx < NN * DD; idx += 256) {
        int i = idx / DD, d = idx - i * DD;
        float v = (d < NC) ? x[(b * NN + i) * NC + d]
                           : ctx[(b * NN + i) * CDIM + (d - NC)];
        zsh[i * ZROW + d] = v;
    }
    __syncthreads();

    // ---- one-time staging: w2h(l=0), ztU, ebh/gwh (both layers) ----
    for (int e = t; e < 1024; e += 256) {
        int kp = e >> 5, c = e & 31;
        int kk = kp >> 2, cqv = kp & 3;
        int p = kk * 8 + cqv;
        uint4 q;
        q.x = g_eW2p[p * 64 + c];
        q.y = g_eW2p[(p + 4) * 64 + c];
        q.z = g_eW2p[p * 64 + c + 32];
        q.w = g_eW2p[(p + 4) * 64 + c + 32];
        *(uint4*)(w2hU + kp * W2HW + c * 4) = q;
    }
    for (int idx = t; idx < 32 * 16; idx += 256) {
        int i = idx >> 4, p = idx & 15;
        uint32_t v = 0;
        if (i < NN && p < 11)
            v = pack_h2(zsh[i * ZROW + 2 * p], zsh[i * ZROW + 2 * p + 1]);
        ztU[i * ZTU + p] = v;
    }
    if (t < 64) {                       // ebh both layers, *0.5
        int ll = t >> 5, i = t & 31;
        int cqv = i >> 3, nf = i & 7;
        ebhU[ll * 32 + cqv * 8 + nf] =
            pack_h2(0.5f * eb2[ll * HDIM + nf * 8 + 2 * cqv],
                    0.5f * eb2[ll * HDIM + nf * 8 + 2 * cqv + 1]);
    } else if (t < 128) {               // gwh both layers
        int i = t - 64;
        int ll = i >> 5; i &= 31;
        int cqv = i >> 3, nf = i & 7;
        gwhU[ll * 32 + cqv * 8 + nf] =
            pack_h2(gW[ll * HDIM + nf * 8 + 2 * cqv],
                    gW[ll * HDIM + nf * 8 + 2 * cqv + 1]);
    }
    __syncthreads();

    for (int l = 0; l < NL; ++l) {
        const float* eb1l = eb1 + l * HDIM;
        const float  gbl  = gb[l];
        const float* lngl = lng + l * DD;
        const float* lnbl = lnb + l * DD;
        const float* nb1l = nb1 + l * HDIM;
        const float* nb2l = nb2 + l * DD;
        const uint32_t* nW1p = g_nW1p + l * (44 * 64);
        const uint32_t* nW2p = g_nW2p + l * (32 * 24);

        // ======== projections via f16 MMA -> piU|pjU (pre-halved) ========
        {
            float pacc[2][2][4];
            #pragma unroll
            for (int mf = 0; mf < 2; ++mf)
                #pragma unroll
                for (int nfi = 0; nfi < 2; ++nfi)
                    #pragma unroll
                    for (int e = 0; e < 4; ++e) pacc[mf][nfi][e] = 0.f;

            const uint32_t* Wp = g_eW1p + (l * 2 + ((w < 4) ? 0 : 1)) * (12 * 64);
            {
                uint32_t aA[2][4];
                #pragma unroll
                for (int mf = 0; mf < 2; ++mf) {
                    int rb = mf * 16;
                    aA[mf][0] = ztU[(rb + lq) * ZTU + cq];
                    aA[mf][1] = ztU[(rb + lq + 8) * ZTU + cq];
                    aA[mf][2] = ztU[(rb + lq) * ZTU + cq + 4];
                    aA[mf][3] = ztU[(rb + lq + 8) * ZTU + cq + 4];
                }
                #pragma unroll
                for (int nfi = 0; nfi < 2; ++nfi) {
                    const int col = (w & 3) * 16 + nfi * 8 + lq;
                    uint32_t b0 = Wp[cq * 64 + col];
                    uint32_t b1 = Wp[(cq + 4) * 64 + col];
                    #pragma unroll
                    for (int mf = 0; mf < 2; ++mf)
                        mma_f16(pacc[mf][nfi], aA[mf][0], aA[mf][1],
                                aA[mf][2], aA[mf][3], b0, b1);
                }
            }
            {
                uint32_t aA[2][2];
                #pragma unroll
                for (int mf = 0; mf < 2; ++mf) {
                    int rb = mf * 16;
                    aA[mf][0] = ztU[(rb + lq) * ZTU + 8 + cq];
                    aA[mf][1] = ztU[(rb + lq + 8) * ZTU + 8 + cq];
                }
                #pragma unroll
                for (int nfi = 0; nfi < 2; ++nfi) {
                    const int col = (w & 3) * 16 + nfi * 8 + lq;
                    uint32_t b0 = Wp[(8 + cq) * 64 + col];
                    #pragma unroll
                    for (int mf = 0; mf < 2; ++mf)
                        mma_f16_k8(pacc[mf][nfi], aA[mf][0], aA[mf][1], b0);
                }
            }
            uint32_t* dstU = (w < 4) ? piU : pjU;
            #pragma unroll
            for (int nfi = 0; nfi < 2; ++nfi) {
                float ex = 0.f, ey = 0.f;
                if (w < 4) {
                    float2 e2 = *(const float2*)(eb1l + (w & 3) * 16 + nfi * 8 + 2 * cq);
                    ex = e2.x; ey = e2.y;
                }
                const int cp = (w & 3) * 8 + cq * 2 + nfi;
                #pragma unroll
                for (int mf = 0; mf < 2; ++mf) {
                    int r = mf * 16 + lq;
                    dstU[r * PRU + cp] =
                        pack_h2((pacc[mf][nfi][0] + ex) * 0.5f,
                                (pacc[mf][nfi][1] + ey) * 0.5f);
                    dstU[(r + 8) * PRU + cp] =
                        pack_h2((pacc[mf][nfi][2] + ex) * 0.5f,
                                (pacc[mf][nfi][3] + ey) * 0.5f);
                }
            }
        }
        // ---- layernorm, parallel: 32 rows x 8 lanes ----
        {
            const int i = t >> 3, j = t & 7;
            float mu = 0.f, sq = 0.f;
            if (i < NN) {
                #pragma unroll
                for (int c = j; c < DD; c += 8) {
                    float v = zsh[i * ZROW + c];
                    mu += v; sq += v * v;
                }
            }
            mu += __shfl_xor_sync(0xffffffffu, mu, 1);
            mu += __shfl_xor_sync(0xffffffffu, mu, 2);
            mu += __shfl_xor_sync(0xffffffffu, mu, 4);
            sq += __shfl_xor_sync(0xffffffffu, sq, 1);
            sq += __shfl_xor_sync(0xffffffffu, sq, 2);
            sq += __shfl_xor_sync(0xffffffffu, sq, 4);
            mu *= (1.0f / DD);
            float var = sq * (1.0f / DD) - mu * mu;
            float rs = rsqrtf(var + 1e-5f);
            if (i < NN) {
                #pragma unroll
                for (int c = j; c < DD; c += 8)
                    znsh[i * ZROW + c] = (zsh[i * ZROW + c] - mu) * rs * lngl[c] + lnbl[c];
            }
        }
        __syncthreads();

        // ---- per-layer hoist: pj pairs ----
        uint2 pj0q[4], pj1q[4];
        {
            const uint2* pj0p = (const uint2*)(pjU + r0 * PRU);
            const uint2* pj1p = (const uint2*)(pjU + r1 * PRU);
            #pragma unroll
            for (int kk = 0; kk < 4; ++kk) {
                pj0q[kk] = pj0p[kk * 4 + cq];
                pj1q[kk] = pj1p[kk * 4 + cq];
            }
        }
        const uint32_t half05 = bcast_h2(0.5f);

        // ======== edge tiles (fully unrolled, predicated body) ========
        #pragma unroll
        for (int ig = 0; ig < 8; ++ig) {
            const int node = ig * 4 + i_sel;
            if (node < NN) {
                const uint2* pi2 = (const uint2*)(piU + node * PRU);

                uint32_t ebr[8], gwh[8];
                *(uint4*)(ebr)     = *(const uint4*)(ebhU + l * 32 + cq * 8);
                *(uint4*)(ebr + 4) = *(const uint4*)(ebhU + l * 32 + cq * 8 + 4);
                *(uint4*)(gwh)     = *(const uint4*)(gwhU + l * 32 + cq * 8);
                *(uint4*)(gwh + 4) = *(const uint4*)(gwhU + l * 32 + cq * 8 + 4);

                float acc[8][4];
                #pragma unroll
                for (int nf = 0; nf < 8; ++nf)
                    #pragma unroll
                    for (int e = 0; e < 4; ++e) acc[nf][e] = 0.f;

                #pragma unroll
                for (int kk = 0; kk < 4; ++kk) {
                    uint2 piq = pi2[kk * 4 + cq];
                    uint32_t a0 = silu_from_h(hadd2u(piq.x, pj0q[kk].x));
                    uint32_t a1 = silu_from_h(hadd2u(piq.x, pj1q[kk].x));
                    uint32_t a2 = silu_from_h(hadd2u(piq.y, pj0q[kk].y));
                    uint32_t a3 = silu_from_h(hadd2u(piq.y, pj1q[kk].y));
                    const uint32_t* wb = w2hU + (kk * 4 + cq) * W2HW + lq * 4;
                    #pragma unroll
                    for (int nf = 0; nf < 4; ++nf) {
                        uint4 q = *(const uint4*)(wb + nf * 32);
                        mma_f16(acc[nf],     a0, a1, a2, a3, q.x, q.y);
                        mma_f16(acc[nf + 4], a0, a1, a2, a3, q.z, q.w);
                    }
                }

                uint32_t m01[8], m23[8];
                uint32_t gph0 = 0, gph1 = 0;
                #pragma unroll
                for (int nf = 0; nf < 8; ++nf) {
                    uint32_t h01 = hfma2u(pack_h2(acc[nf][0], acc[nf][1]), half05, ebr[nf]);
                    uint32_t h23 = hfma2u(pack_h2(acc[nf][2], acc[nf][3]), half05, ebr[nf]);
                    uint32_t u01 = silu_from_h(h01);
                    uint32_t u23 = silu_from_h(h23);
                    m01[nf] = u01; m23[nf] = u23;
                    gph0 = hfma2u(u01, gwh[nf], gph0);
                    gph1 = hfma2u(u23, gwh[nf], gph1);
                }
                float2 gpf0 = h22f2(gph0), gpf1 = h22f2(gph1);
                float gp0 = gpf0.x + gpf0.y;
                float gp1 = gpf1.x + gpf1.y;
                gp0 += __shfl_xor_sync(0xffffffffu, gp0, 1);
                gp0 += __shfl_xor_sync(0xffffffffu, gp0, 2);
                gp1 += __shfl_xor_sync(0xffffffffu, gp1, 1);
                gp1 += __shfl_xor_sync(0xffffffffu, gp1, 2);
                float g0 = sigm_t(gp0 + gbl);
                float g1 = (r1 < NN) ? sigm_t(gp1 + gbl) : 0.f;
                uint32_t g0h = bcast_h2(g0), g1h = bcast_h2(g1);

                uint32_t s8h[8];
                #pragma unroll
                for (int nf = 0; nf < 8; ++nf)
                    s8h[nf] = hfma2u(m23[nf], g1h, hmul2u(m01[nf], g0h));

                const int bb0 = lq & 1, bb1 = (lq >> 1) & 1, bb2 = (lq >> 2) & 1;
                uint32_t v4h[4];
                #pragma unroll
                for (int j = 0; j < 4; ++j) {
                    uint32_t keep = bb0 ? s8h[4 + j] : s8h[j];
                    uint32_t send = bb0 ? s8h[j]     : s8h[4 + j];
                    v4h[j] = hadd2u(keep, __shfl_xor_sync(0xffffffffu, send, 4));
                }
                uint32_t v2h[2];
                #pragma unroll
                for (int j = 0; j < 2; ++j) {
                    uint32_t keep = bb1 ? v4h[2 + j] : v4h[j];
                    uint32_t send = bb1 ? v4h[j]     : v4h[2 + j];
                    v2h[j] = hadd2u(keep, __shfl_xor_sync(0xffffffffu, send, 8));
                }
                const int pbase = bb0 * 4 + bb1 * 2;
                uint32_t* mg = maggU + (jh * 2 + bb2) * MPL + node * MAGU;
                mg[pbase * 4 + cq]       = v2h[0];
                mg[(pbase + 1) * 4 + cq] = v2h[1];
            }
        }
        __syncthreads();

        // ======== combine 4 planes + catsh; overlap next-layer w2h staging ========
        for (int idx = t; idx < NN * 32; idx += 256) {
            uint32_t v = hadd2u(hadd2u(maggU[idx],           maggU[MPL + idx]),
                                hadd2u(maggU[2 * MPL + idx], maggU[3 * MPL + idx]));
            int i = idx >> 5, p = idx & 31;
            catshU[i * CATU + 11 + p] = v;
        }
        for (int idx = t; idx < 3 * 32; idx += 256) {
            int i = NN + (idx >> 5), p = idx & 31;
            catshU[i * CATU + 11 + p] = 0;
        }
        for (int idx = t; idx < 32 * 16; idx += 256) {
            int i = idx >> 4, p = idx & 15;
            if (p < 11) {
                uint32_t v = 0;
                if (i < NN) v = pack_h2(znsh[i * ZROW + 2 * p], znsh[i * ZROW + 2 * p + 1]);
                catshU[i * CATU + p] = v;
            } else {
                catshU[i * CATU + 32 + p] = 0;
            }
        }
        if (l + 1 < NL) {   // stage next layer's W2 (w2hU free after tile barrier)
            const uint32_t* eW2n = g_eW2p + (l + 1) * 2048;
            for (int e = t; e < 1024; e += 256) {
                int kp = e >> 5, c = e & 31;
                int kk = kp >> 2, cqv = kp & 3;
                int p = kk * 8 + cqv;
                uint4 q;
                q.x = eW2n[p * 64 + c];
                q.y = eW2n[(p + 4) * 64 + c];
                q.z = eW2n[p * 64 + c + 32];
                q.w = eW2n[(p + 4) * 64 + c + 32];
                *(uint4*)(w2hU + kp * W2HW + c * 4) = q;
            }
        }
        __syncthreads();

        // ======== node MLP layer 1 via f16 MMA: [32x88] @ [86x64] ========
        {
            const int mh  = w & 1;
            const int nh4 = w >> 1;
            const int row0 = mh * 16 + lq, row1 = row0 + 8;
            float c2[2][4];
            #pragma unroll
            for (int nfi = 0; nfi < 2; ++nfi)
                #pragma unroll
                for (int e = 0; e < 4; ++e) c2[nfi][e] = 0.f;

            #pragma unroll
            for (int kk = 0; kk < 5; ++kk) {
                uint32_t a0 = catshU[row0 * CATU + kk * 8 + cq];
                uint32_t a1 = catshU[row1 * CATU + kk * 8 + cq];
                uint32_t a2 = catshU[row0 * CATU + kk * 8 + cq + 4];
                uint32_t a3 = catshU[row1 * CATU + kk * 8 + cq + 4];
                #pragma unroll
                for (int nfi = 0; nfi < 2; ++nfi) {
                    const int col = (nh4 * 2 + nfi) * 8 + lq;
                    uint32_t b0 = nW1p[(kk * 8 + cq) * 64 + col];
                    uint32_t b1 = nW1p[(kk * 8 + cq + 4) * 64 + col];
                    mma_f16(c2[nfi], a0, a1, a2, a3, b0, b1);
                }
            }
            {
                uint32_t a0 = catshU[row0 * CATU + 40 + cq];
                uint32_t a1 = catshU[row1 * CATU + 40 + cq];
                #pragma unroll
                for (int nfi = 0; nfi < 2; ++nfi) {
                    const int col = (nh4 * 2 + nfi) * 8 + lq;
                    uint32_t b0 = nW1p[(40 + cq) * 64 + col];
                    mma_f16_k8(c2[nfi], a0, a1, b0);
                }
            }
            #pragma unroll
            for (int nfi = 0; nfi < 2; ++nfi) {
                const int colb = (nh4 * 2 + nfi) * 8 + 2 * cq;
                float2 nb = *(const float2*)(nb1l + colb);
                const int pid = colb >> 1;
                hbufU[row0 * HBU + pid] =
                    pack_h2(silu_t(c2[nfi][0] + nb.x), silu_t(c2[nfi][1] + nb.y));
                hbufU[row1 * HBU + pid] =
                    pack_h2(silu_t(c2[nfi][2] + nb.x), silu_t(c2[nfi][3] + nb.y));
            }
        }
        __syncthreads();

        // ======== node MLP layer 2 via f16 MMA + residual; writes zsh AND ztU ========
        if (w < 6) {
            const int mf = w & 1;
            const int nf = w >> 1;
            const int d0 = nf * 8 + lq;
            const int rr0 = mf * 16 + lq, rr1 = rr0 + 8;
            float c4[4] = {0.f, 0.f, 0.f, 0.f};
            #pragma unroll
            for (int kk = 0; kk < 4; ++kk) {
                uint32_t a0 = hbufU[rr0 * HBU + kk * 8 + cq];
                uint32_t a1 = hbufU[rr1 * HBU + kk * 8 + cq];
                uint32_t a2 = hbufU[rr0 * HBU + kk * 8 + cq + 4];
                uint32_t a3 = hbufU[rr1 * HBU + kk * 8 + cq + 4];
                uint32_t b0 = nW2p[(kk * 8 + cq) * 24 + d0];
                uint32_t b1 = nW2p[(kk * 8 + cq + 4) * 24 + d0];
                mma_f16(c4, a0, a1, a2, a3, b0, b1);
            }
            const int col = nf * 8 + 2 * cq;
            if (col < DD) {
                float nb0 = nb2l[col];
                float nb1v = nb2l[col + 1];
                if (rr0 < NN) {
                    float z0 = zsh[rr0 * ZROW + col] + c4[0] + nb0;
                    float z1 = zsh[rr0 * ZROW + col + 1] + c4[1] + nb1v;
                    zsh[rr0 * ZROW + col] = z0;
                    zsh[rr0 * ZROW + col + 1] = z1;
                    ztU[rr0 * ZTU + (col >> 1)] = pack_h2(z0, z1);
                }
                if (rr1 < NN) {
                    float z0 = zsh[rr1 * ZROW + col] + c4[2] + nb0;
                    float z1 = zsh[rr1 * ZROW + col + 1] + c4[3] + nb1v;
                    zsh[rr1 * ZROW + col] = z0;
                    zsh[rr1 * ZROW + col + 1] = z1;
                    ztU[rr1 * ZTU + (col >> 1)] = pack_h2(z0, z1);
                }
            }
        }
        __syncthreads();
    }

    // ---- mean pool ----
    if (t < DD) {
        float s = 0.f;
        #pragma unroll
        for (int i = 0; i < NN; ++i) s += zsh[i * ZROW + t];
        znsh[t] = s * (1.0f / NN);
    }
    __syncthreads();

    // ---- head MLP ----
    float* hscr = znsh + 64;
    if (t < HDIM) {
        float a = hb1[t];
        #pragma unroll
        for (int d = 0; d < DD; ++d) a += znsh[d] * hW1[d * HDIM + t];
        hscr[t] = fmaxf(a, 0.f);
    }
    __syncthreads();

    float* ob = out + (size_t)b * (NN * OUTROW);
    for (int idx = t; idx < NN * OUTROW; idx += 256) {
        float v = 0.f;
        if (idx < NOUT) {
            v = hb2[idx];
            #pragma unroll
            for (int m2 = 0; m2 < HDIM; ++m2)
                v += hscr[m2] * hW2[m2 * NOUT + idx];
        }
        ob[idx] = v;
    }
}

extern "C" void kernel_launch(void* const* d_in, const int* in_sizes, int n_in,
                              void* d_out, int out_size) {
    (void)in_sizes; (void)n_in; (void)out_size;
    const float* x    = (const float*)d_in[0];
    const float* ctx  = (const float*)d_in[1];
    const float* eW1  = (const float*)d_in[2];
    const float* eb1  = (const float*)d_in[3];
    const float* eW2  = (const float*)d_in[4];
    const float* eb2  = (const float*)d_in[5];
    const float* gW   = (const float*)d_in[6];
    const float* gb   = (const float*)d_in[7];
    const float* lng  = (const float*)d_in[8];
    const float* lnb  = (const float*)d_in[9];
    const float* nW1  = (const float*)d_in[10];
    const float* nb1  = (const float*)d_in[11];
    const float* nW2  = (const float*)d_in[12];
    const float* nb2  = (const float*)d_in[13];
    const float* hW1  = (const float*)d_in[14];
    const float* hb1  = (const float*)d_in[15];
    const float* hW2  = (const float*)d_in[16];
    const float* hb2  = (const float*)d_in[17];
    float* out = (float*)d_out;

    prep_pack<<<32, 256>>>(eW1, eW2, nW1, nW2);
    cudaFuncSetAttribute(gnn_kernel, cudaFuncAttributeMaxDynamicSharedMemorySize,
                         SMEM_FLOATS * sizeof(float));
    gnn_kernel<<<NB, 256, SMEM_FLOATS * sizeof(float)>>>(
        x, ctx, eb1, eb2, gW, gb, lng, lnb,
        nb1, nb2, hW1, hb1, hW2, hb2, out);
}